// round 4
// baseline (speedup 1.0000x reference)
#include <cuda_runtime.h>
#include <cuda_bf16.h>
#include <stdint.h>

// Problem constants (from reference)
#define C 64
#define H 8
#define MAXN 100000
#define NEG_SLOPE 0.01f

// Node tables: per node, two float4 = (p, q0, q1, q2) and (q3, pad, pad, pad),
// for row-role (T0: first half of coef) and col-role (T1: second half).
// 100k * 32B * 2 = 6.4 MB -> resident in L2 during the edge kernel.
// Declared as float4 so the base is 16B-aligned for LDG.128/STG.128.
__device__ float4 g_T0[MAXN * 2];
__device__ float4 g_T1[MAXN * 2];

// ---------------------------------------------------------------------------
// Kernel 1: per-node precompute.
// One warp per node; lane handles channels (lane, lane+32).
//   p0 = x . b[0:64]      q0[k] = sum_j x[j] * W[j][k]        (k=0..3)
//   p1 = x . b[64:128]    q1[k] = sum_j x[j] * W[64+j][k]
// where b[j] = psi_b[j] + delta_w[li][j] + u[li][j], W = psi_w [128,4] row-major.
// ---------------------------------------------------------------------------
__global__ void node_precompute(const float* __restrict__ x,
                                const float* __restrict__ psi_w,
                                const float* __restrict__ psi_b,
                                const float* __restrict__ delta_w,
                                const float* __restrict__ uvec,
                                const int*   __restrict__ li_ptr,
                                int n_nodes)
{
    __shared__ float s_b[2 * C];       // 128
    __shared__ float s_w[2 * C * 4];   // 512

    const int li = li_ptr[0];
    const int tid = threadIdx.x;

    // Cooperative load of small params into shared
    for (int j = tid; j < 2 * C; j += blockDim.x)
        s_b[j] = psi_b[j] + delta_w[li * 2 * C + j] + uvec[li * 2 * C + j];
    for (int j = tid; j < 2 * C * 4; j += blockDim.x)
        s_w[j] = psi_w[j];
    __syncthreads();

    const int warp = tid >> 5;
    const int lane = tid & 31;
    const int node = blockIdx.x * (blockDim.x >> 5) + warp;
    if (node >= n_nodes) return;

    const int c0 = lane;
    const int c1 = lane + 32;
    const float x0 = x[(size_t)node * C + c0];
    const float x1 = x[(size_t)node * C + c1];

    float acc[10];
    // p0
    acc[0] = x0 * s_b[c0] + x1 * s_b[c1];
    // q0[k]
    #pragma unroll
    for (int k = 0; k < 4; k++)
        acc[1 + k] = x0 * s_w[c0 * 4 + k] + x1 * s_w[c1 * 4 + k];
    // p1
    acc[5] = x0 * s_b[C + c0] + x1 * s_b[C + c1];
    // q1[k]
    #pragma unroll
    for (int k = 0; k < 4; k++)
        acc[6 + k] = x0 * s_w[(C + c0) * 4 + k] + x1 * s_w[(C + c1) * 4 + k];

    // Warp butterfly reduction of all 10 accumulators
    #pragma unroll
    for (int off = 16; off > 0; off >>= 1) {
        #pragma unroll
        for (int i = 0; i < 10; i++)
            acc[i] += __shfl_xor_sync(0xFFFFFFFFu, acc[i], off);
    }

    if (lane == 0) {
        g_T0[(size_t)node * 2 + 0] = make_float4(acc[0], acc[1], acc[2], acc[3]);
        g_T0[(size_t)node * 2 + 1] = make_float4(acc[4], 0.f, 0.f, 0.f);
        g_T1[(size_t)node * 2 + 0] = make_float4(acc[5], acc[6], acc[7], acc[8]);
        g_T1[(size_t)node * 2 + 1] = make_float4(acc[9], 0.f, 0.f, 0.f);
    }
}

// ---------------------------------------------------------------------------
// Kernel 2: per-edge. One thread per edge.
//   s = p0[row] + sf . q0[row] + p1[col] + sf . q1[col]
//   base = leaky_relu(s); out[e][h] = gamma[h] * base
// NOTE: edge_index is int32 (JAX x64 disabled -> jnp.int64 degrades to int32).
// ---------------------------------------------------------------------------
__global__ void edge_kernel(const int* __restrict__ edge_index,
                            const float* __restrict__ sf,
                            const float* __restrict__ gamma_h,
                            const int*   __restrict__ li_ptr,
                            float* __restrict__ out,
                            int n_edges)
{
    __shared__ float s_g[H];
    const int li = li_ptr[0];
    if (threadIdx.x < H) s_g[threadIdx.x] = gamma_h[li * H + threadIdx.x];
    __syncthreads();

    const int e = blockIdx.x * blockDim.x + threadIdx.x;
    if (e >= n_edges) return;

    const int row = edge_index[e];
    const int col = edge_index[n_edges + e];

    const float4 f = __ldg(reinterpret_cast<const float4*>(sf) + e);

    const float4 r0 = __ldg(&g_T0[(size_t)row * 2 + 0]);
    const float4 r1 = __ldg(&g_T0[(size_t)row * 2 + 1]);
    const float4 c0 = __ldg(&g_T1[(size_t)col * 2 + 0]);
    const float4 c1 = __ldg(&g_T1[(size_t)col * 2 + 1]);

    float s = r0.x + c0.x;
    s = fmaf(f.x, r0.y, s);
    s = fmaf(f.y, r0.z, s);
    s = fmaf(f.z, r0.w, s);
    s = fmaf(f.w, r1.x, s);
    s = fmaf(f.x, c0.y, s);
    s = fmaf(f.y, c0.z, s);
    s = fmaf(f.z, c0.w, s);
    s = fmaf(f.w, c1.x, s);

    const float base = (s > 0.f) ? s : NEG_SLOPE * s;

    float4 o0 = make_float4(s_g[0] * base, s_g[1] * base, s_g[2] * base, s_g[3] * base);
    float4 o1 = make_float4(s_g[4] * base, s_g[5] * base, s_g[6] * base, s_g[7] * base);
    float4* op = reinterpret_cast<float4*>(out + (size_t)e * H);
    op[0] = o0;
    op[1] = o1;
}

// ---------------------------------------------------------------------------
// Launch. Input order (metadata): x, edge_index, structural_features,
// layer_idx, psi_w, psi_b, delta_w, u, gamma_h.
// ---------------------------------------------------------------------------
extern "C" void kernel_launch(void* const* d_in, const int* in_sizes, int n_in,
                              void* d_out, int out_size)
{
    const float* x    = (const float*)d_in[0];
    const int*   ei   = (const int*)d_in[1];
    const float* sf   = (const float*)d_in[2];
    const int*   li   = (const int*)d_in[3];
    const float* pw   = (const float*)d_in[4];
    const float* pb   = (const float*)d_in[5];
    const float* dw   = (const float*)d_in[6];
    const float* uu   = (const float*)d_in[7];
    const float* gh   = (const float*)d_in[8];
    float*       out  = (float*)d_out;

    const int n_nodes = in_sizes[0] / C;
    const int n_edges = in_sizes[1] / 2;

    // Kernel 1: 8 warps/block -> 8 nodes per block
    {
        const int threads = 256;
        const int nodes_per_block = threads / 32;
        const int blocks = (n_nodes + nodes_per_block - 1) / nodes_per_block;
        node_precompute<<<blocks, threads>>>(x, pw, pb, dw, uu, li, n_nodes);
    }

    // Kernel 2: 1 thread/edge
    {
        const int threads = 256;
        const int blocks = (n_edges + threads - 1) / threads;
        edge_kernel<<<blocks, threads>>>(ei, sf, gh, li, out, n_edges);
    }
}

// round 9
// speedup vs baseline: 1.1596x; 1.1596x over previous
#include <cuda_runtime.h>
#include <cuda_bf16.h>
#include <cuda_fp16.h>
#include <stdint.h>

#define C 64
#define H 8
#define MAXN 100000
#define NEG_SLOPE 0.01f

// Compressed node tables: one float4 (16B) per node per role:
//   .x = p (fp32), .y = half2(q0,q1), .z = half2(q2,q3), .w unused.
// 100k * 16B * 2 = 3.2 MB -> L2-resident during the edge kernel.
// One LDG.128 per role per edge (was two) -> halves L1tex gather wavefronts.
__device__ float4 g_T0[MAXN];
__device__ float4 g_T1[MAXN];

// ---------------------------------------------------------------------------
// Kernel 1: per-node precompute, persistent grid-stride (preamble loaded once
// per block, not once per 8 nodes).
// One warp per node; lane handles channels (lane, lane+32).
//   p0 = x . b[0:64]      q0[k] = sum_j x[j] * W[j][k]
//   p1 = x . b[64:128]    q1[k] = sum_j x[j] * W[64+j][k]
// b[j] = psi_b[j] + delta_w[li][j] + u[li][j];  W = psi_w [128,4] row-major.
// ---------------------------------------------------------------------------
__global__ void node_precompute(const float* __restrict__ x,
                                const float* __restrict__ psi_w,
                                const float* __restrict__ psi_b,
                                const float* __restrict__ delta_w,
                                const float* __restrict__ uvec,
                                const int*   __restrict__ li_ptr,
                                int n_nodes)
{
    __shared__ float s_b[2 * C];       // 128
    __shared__ float s_w[2 * C * 4];   // 512

    const int li = li_ptr[0];
    const int tid = threadIdx.x;

    for (int j = tid; j < 2 * C; j += blockDim.x)
        s_b[j] = psi_b[j] + delta_w[li * 2 * C + j] + uvec[li * 2 * C + j];
    for (int j = tid; j < 2 * C * 4; j += blockDim.x)
        s_w[j] = psi_w[j];
    __syncthreads();

    const int warp = tid >> 5;
    const int lane = tid & 31;
    const int warps_per_block = blockDim.x >> 5;
    const int stride = gridDim.x * warps_per_block;

    const int c0 = lane;
    const int c1 = lane + 32;

    // Hoist weights into registers (loop-invariant across nodes)
    const float b00 = s_b[c0],     b01 = s_b[c1];
    const float b10 = s_b[C + c0], b11 = s_b[C + c1];
    float w0[4], w1[4], w2[4], w3[4];
    #pragma unroll
    for (int k = 0; k < 4; k++) {
        w0[k] = s_w[c0 * 4 + k];
        w1[k] = s_w[c1 * 4 + k];
        w2[k] = s_w[(C + c0) * 4 + k];
        w3[k] = s_w[(C + c1) * 4 + k];
    }

    for (int node = blockIdx.x * warps_per_block + warp; node < n_nodes;
         node += stride)
    {
        const float x0 = x[(size_t)node * C + c0];
        const float x1 = x[(size_t)node * C + c1];

        float acc[10];
        acc[0] = x0 * b00 + x1 * b01;
        #pragma unroll
        for (int k = 0; k < 4; k++) acc[1 + k] = x0 * w0[k] + x1 * w1[k];
        acc[5] = x0 * b10 + x1 * b11;
        #pragma unroll
        for (int k = 0; k < 4; k++) acc[6 + k] = x0 * w2[k] + x1 * w3[k];

        #pragma unroll
        for (int off = 16; off > 0; off >>= 1) {
            #pragma unroll
            for (int i = 0; i < 10; i++)
                acc[i] += __shfl_xor_sync(0xFFFFFFFFu, acc[i], off);
        }

        if (lane == 0) {
            __half2 a01 = __floats2half2_rn(acc[1], acc[2]);
            __half2 a23 = __floats2half2_rn(acc[3], acc[4]);
            __half2 b01h = __floats2half2_rn(acc[6], acc[7]);
            __half2 b23h = __floats2half2_rn(acc[8], acc[9]);
            float4 t0, t1;
            t0.x = acc[0];
            t0.y = __uint_as_float(*reinterpret_cast<unsigned*>(&a01));
            t0.z = __uint_as_float(*reinterpret_cast<unsigned*>(&a23));
            t0.w = 0.f;
            t1.x = acc[5];
            t1.y = __uint_as_float(*reinterpret_cast<unsigned*>(&b01h));
            t1.z = __uint_as_float(*reinterpret_cast<unsigned*>(&b23h));
            t1.w = 0.f;
            g_T0[node] = t0;
            g_T1[node] = t1;
        }
    }
}

// ---------------------------------------------------------------------------
// Kernel 2: per-edge. One thread per edge. Two 16B gathers (was four).
//   s = p0[row] + p1[col] + sf . (q0[row] + q1[col])
// edge_index is int32 (JAX x64 disabled).
// ---------------------------------------------------------------------------
__global__ void edge_kernel(const int* __restrict__ edge_index,
                            const float* __restrict__ sf,
                            const float* __restrict__ gamma_h,
                            const int*   __restrict__ li_ptr,
                            float* __restrict__ out,
                            int n_edges)
{
    __shared__ float s_g[H];
    const int li = li_ptr[0];
    if (threadIdx.x < H) s_g[threadIdx.x] = gamma_h[li * H + threadIdx.x];
    __syncthreads();

    const int e = blockIdx.x * blockDim.x + threadIdx.x;
    if (e >= n_edges) return;

    const int row = edge_index[e];
    const int col = edge_index[n_edges + e];

    const float4 f = __ldg(reinterpret_cast<const float4*>(sf) + e);
    const float4 R  = __ldg(&g_T0[row]);
    const float4 Cc = __ldg(&g_T1[col]);

    const __half2 rq01 = *reinterpret_cast<const __half2*>(&R.y);
    const __half2 rq23 = *reinterpret_cast<const __half2*>(&R.z);
    const __half2 cq01 = *reinterpret_cast<const __half2*>(&Cc.y);
    const __half2 cq23 = *reinterpret_cast<const __half2*>(&Cc.z);

    const float2 q01 = __half22float2(__hadd2(rq01, cq01));
    const float2 q23 = __half22float2(__hadd2(rq23, cq23));

    float s = R.x + Cc.x;
    s = fmaf(f.x, q01.x, s);
    s = fmaf(f.y, q01.y, s);
    s = fmaf(f.z, q23.x, s);
    s = fmaf(f.w, q23.y, s);

    const float base = (s > 0.f) ? s : NEG_SLOPE * s;

    float4 o0 = make_float4(s_g[0] * base, s_g[1] * base, s_g[2] * base, s_g[3] * base);
    float4 o1 = make_float4(s_g[4] * base, s_g[5] * base, s_g[6] * base, s_g[7] * base);
    float4* op = reinterpret_cast<float4*>(out + (size_t)e * H);
    op[0] = o0;
    op[1] = o1;
}

// ---------------------------------------------------------------------------
// Launch. Input order: x, edge_index, structural_features, layer_idx,
// psi_w, psi_b, delta_w, u, gamma_h.
// ---------------------------------------------------------------------------
extern "C" void kernel_launch(void* const* d_in, const int* in_sizes, int n_in,
                              void* d_out, int out_size)
{
    const float* x    = (const float*)d_in[0];
    const int*   ei   = (const int*)d_in[1];
    const float* sf   = (const float*)d_in[2];
    const int*   li   = (const int*)d_in[3];
    const float* pw   = (const float*)d_in[4];
    const float* pb   = (const float*)d_in[5];
    const float* dw   = (const float*)d_in[6];
    const float* uu   = (const float*)d_in[7];
    const float* gh   = (const float*)d_in[8];
    float*       out  = (float*)d_out;

    const int n_nodes = in_sizes[0] / C;
    const int n_edges = in_sizes[1] / 2;

    // Kernel 1: persistent blocks, 8 warps each, grid-stride over nodes.
    // Cap grid at what the node count actually needs.
    {
        const int threads = 256;
        const int warps_per_block = threads / 32;
        int blocks = 148 * 8;  // full-chip persistent occupancy
        int needed = (n_nodes + warps_per_block - 1) / warps_per_block;
        if (blocks > needed) blocks = needed;
        node_precompute<<<blocks, threads>>>(x, pw, pb, dw, uu, li, n_nodes);
    }

    // Kernel 2: 1 thread/edge
    {
        const int threads = 256;
        const int blocks = (n_edges + threads - 1) / threads;
        edge_kernel<<<blocks, threads>>>(ei, sf, gh, li, out, n_edges);
    }
}

// round 11
// speedup vs baseline: 1.8387x; 1.5856x over previous
#include <cuda_runtime.h>
#include <cuda_bf16.h>
#include <cuda_fp16.h>
#include <stdint.h>

#define C 64
#define H 8
#define MAXN 100000
#define NEG_SLOPE 0.01f
#define TILE 128          // nodes per block in node kernel
#define XPAD 65           // smem row stride in floats (conflict-free scalar LDS)

// Compressed node tables: one float4 (16B) per node per role:
//   .x = p (fp32), .y = half2(q0,q1), .z = half2(q2,q3), .w unused.
// 100k * 16B * 2 = 3.2 MB -> L2-resident during the edge kernel.
__device__ float4 g_T0[MAXN];
__device__ float4 g_T1[MAXN];

// ---------------------------------------------------------------------------
// Kernel 1: per-node precompute, THREAD-per-node (no warp shuffles at all —
// the previous warp-per-node version was SHFL/MIO-throughput-bound).
//   p0 = x . b[0:64]      q0[k] = sum_j x[j] * W[j][k]
//   p1 = x . b[64:128]    q1[k] = sum_j x[j] * W[64+j][k]
// b[j] = psi_b[j] + delta_w[li][j] + u[li][j];  W = psi_w [128,4] row-major.
//
// Coefficients staged in smem as [j][12]: {b[j], W[j][0..3], b[64+j],
// W[64+j][0..3], pad, pad} -> three uniform (broadcast) LDS.128 per j.
// x tile staged coalesced into smem padded to 65 floats/row: per-iteration
// scalar read s_x[n*65+j] maps to bank (n+j)%32 -> conflict-free.
// ---------------------------------------------------------------------------
__global__ void node_precompute(const float* __restrict__ x,
                                const float* __restrict__ psi_w,
                                const float* __restrict__ psi_b,
                                const float* __restrict__ delta_w,
                                const float* __restrict__ uvec,
                                const int*   __restrict__ li_ptr,
                                int n_nodes)
{
    __shared__ float s_x[TILE * XPAD];                 // 33.3 KB
    __shared__ __align__(16) float s_c[C * 12];        // 3 KB

    const int tid = threadIdx.x;
    const int li  = li_ptr[0];

    // Build coefficient table (threads 0..63, one j each)
    if (tid < C) {
        const int j = tid;
        float* c = &s_c[j * 12];
        c[0] = psi_b[j] + delta_w[li * 2 * C + j] + uvec[li * 2 * C + j];
        #pragma unroll
        for (int k = 0; k < 4; k++) c[1 + k] = psi_w[j * 4 + k];
        c[5] = psi_b[C + j] + delta_w[li * 2 * C + C + j] + uvec[li * 2 * C + C + j];
        #pragma unroll
        for (int k = 0; k < 4; k++) c[6 + k] = psi_w[(C + j) * 4 + k];
        c[10] = 0.f; c[11] = 0.f;
    }

    const int node0 = blockIdx.x * TILE;

    // Coalesced load of the x tile (TILE nodes x 16 float4 each)
    const float4* x4 = reinterpret_cast<const float4*>(x);
    for (int i = tid; i < TILE * 16; i += blockDim.x) {
        const int n  = i >> 4;
        const int j4 = i & 15;
        if (node0 + n < n_nodes) {
            float4 v = x4[(size_t)(node0 + n) * 16 + j4];
            float* dst = &s_x[n * XPAD + j4 * 4];
            dst[0] = v.x; dst[1] = v.y; dst[2] = v.z; dst[3] = v.w;
        }
    }
    __syncthreads();

    const int node = node0 + tid;
    if (node >= n_nodes) return;

    const float* xr = &s_x[tid * XPAD];
    float a0 = 0.f, a1 = 0.f, a2 = 0.f, a3 = 0.f, a4 = 0.f;
    float a5 = 0.f, a6 = 0.f, a7 = 0.f, a8 = 0.f, a9 = 0.f;

    #pragma unroll 8
    for (int j = 0; j < C; j++) {
        const float xv = xr[j];
        const float4* c4 = reinterpret_cast<const float4*>(&s_c[j * 12]);
        const float4 cA = c4[0];   // b1, w0, w1, w2
        const float4 cB = c4[1];   // w3, b2, w0', w1'
        const float4 cC = c4[2];   // w2', w3', pad, pad
        a0 = fmaf(xv, cA.x, a0);
        a1 = fmaf(xv, cA.y, a1);
        a2 = fmaf(xv, cA.z, a2);
        a3 = fmaf(xv, cA.w, a3);
        a4 = fmaf(xv, cB.x, a4);
        a5 = fmaf(xv, cB.y, a5);
        a6 = fmaf(xv, cB.z, a6);
        a7 = fmaf(xv, cB.w, a7);
        a8 = fmaf(xv, cC.x, a8);
        a9 = fmaf(xv, cC.y, a9);
    }

    // Pack: T0 = {p0, h2(q0,q1), h2(q2,q3)}, T1 likewise for the col role.
    __half2 q01  = __floats2half2_rn(a1, a2);
    __half2 q23  = __floats2half2_rn(a3, a4);
    __half2 q01b = __floats2half2_rn(a6, a7);
    __half2 q23b = __floats2half2_rn(a8, a9);
    float4 t0, t1;
    t0.x = a0;
    t0.y = __uint_as_float(*reinterpret_cast<unsigned*>(&q01));
    t0.z = __uint_as_float(*reinterpret_cast<unsigned*>(&q23));
    t0.w = 0.f;
    t1.x = a5;
    t1.y = __uint_as_float(*reinterpret_cast<unsigned*>(&q01b));
    t1.z = __uint_as_float(*reinterpret_cast<unsigned*>(&q23b));
    t1.w = 0.f;
    g_T0[node] = t0;   // consecutive threads -> consecutive 16B: coalesced
    g_T1[node] = t1;
}

// ---------------------------------------------------------------------------
// Kernel 2: per-edge. One thread per edge. Two 16B gathers.
//   s = p0[row] + p1[col] + sf . (q0[row] + q1[col])
// edge_index is int32 (JAX x64 disabled).
// ---------------------------------------------------------------------------
__global__ void edge_kernel(const int* __restrict__ edge_index,
                            const float* __restrict__ sf,
                            const float* __restrict__ gamma_h,
                            const int*   __restrict__ li_ptr,
                            float* __restrict__ out,
                            int n_edges)
{
    __shared__ float s_g[H];
    const int li = li_ptr[0];
    if (threadIdx.x < H) s_g[threadIdx.x] = gamma_h[li * H + threadIdx.x];
    __syncthreads();

    const int e = blockIdx.x * blockDim.x + threadIdx.x;
    if (e >= n_edges) return;

    const int row = edge_index[e];
    const int col = edge_index[n_edges + e];

    const float4 f = __ldg(reinterpret_cast<const float4*>(sf) + e);
    const float4 R  = __ldg(&g_T0[row]);
    const float4 Cc = __ldg(&g_T1[col]);

    const __half2 rq01 = *reinterpret_cast<const __half2*>(&R.y);
    const __half2 rq23 = *reinterpret_cast<const __half2*>(&R.z);
    const __half2 cq01 = *reinterpret_cast<const __half2*>(&Cc.y);
    const __half2 cq23 = *reinterpret_cast<const __half2*>(&Cc.z);

    const float2 q01 = __half22float2(__hadd2(rq01, cq01));
    const float2 q23 = __half22float2(__hadd2(rq23, cq23));

    float s = R.x + Cc.x;
    s = fmaf(f.x, q01.x, s);
    s = fmaf(f.y, q01.y, s);
    s = fmaf(f.z, q23.x, s);
    s = fmaf(f.w, q23.y, s);

    const float base = (s > 0.f) ? s : NEG_SLOPE * s;

    float4 o0 = make_float4(s_g[0] * base, s_g[1] * base, s_g[2] * base, s_g[3] * base);
    float4 o1 = make_float4(s_g[4] * base, s_g[5] * base, s_g[6] * base, s_g[7] * base);
    float4* op = reinterpret_cast<float4*>(out + (size_t)e * H);
    op[0] = o0;
    op[1] = o1;
}

// ---------------------------------------------------------------------------
// Launch. Input order: x, edge_index, structural_features, layer_idx,
// psi_w, psi_b, delta_w, u, gamma_h.
// ---------------------------------------------------------------------------
extern "C" void kernel_launch(void* const* d_in, const int* in_sizes, int n_in,
                              void* d_out, int out_size)
{
    const float* x    = (const float*)d_in[0];
    const int*   ei   = (const int*)d_in[1];
    const float* sf   = (const float*)d_in[2];
    const int*   li   = (const int*)d_in[3];
    const float* pw   = (const float*)d_in[4];
    const float* pb   = (const float*)d_in[5];
    const float* dw   = (const float*)d_in[6];
    const float* uu   = (const float*)d_in[7];
    const float* gh   = (const float*)d_in[8];
    float*       out  = (float*)d_out;

    const int n_nodes = in_sizes[0] / C;
    const int n_edges = in_sizes[1] / 2;

    // Kernel 1: thread-per-node, 128-node tiles
    {
        const int threads = TILE;
        const int blocks  = (n_nodes + TILE - 1) / TILE;
        node_precompute<<<blocks, threads>>>(x, pw, pb, dw, uu, li, n_nodes);
    }

    // Kernel 2: 1 thread/edge
    {
        const int threads = 256;
        const int blocks = (n_edges + threads - 1) / threads;
        edge_kernel<<<blocks, threads>>>(ei, sf, gh, li, out, n_edges);
    }
}